// round 11
// baseline (speedup 1.0000x reference)
#include <cuda_runtime.h>
#include <math.h>

// Fixed shapes: xs/hat_xs are (16, 65536, 3) float32 -> 1,048,576 vectors, 65,536 groups of 16.
#define NGROUPS      65536
#define GPB          64                     // groups per block
#define THREADS      256                    // 4 threads per group in phase A
#define NBLOCKS      (NGROUPS / GPB)        // 1024
#define PAIRS_MASK   2047
#define N0_DROP      5
#define DT           0.01f
#define INV_HUBER    200.0f
#define AOE_COEF     (0.2f / 65536.0f)
#define HUB_COEF     (1.25f / 98064.0f)     // 0.1*W*HUBER^2/2 / (16*2043*3)
#define PI_F         3.14159265358979f

// q = (x,y,z,w), w scalar. Hamilton product (R(a)R(b)).
__device__ __forceinline__ float4 qmul(float4 a, float4 b) {
    float4 r;
    r.w = a.w * b.w - a.x * b.x - a.y * b.y - a.z * b.z;
    r.x = a.w * b.x + a.x * b.w + a.y * b.z - a.z * b.y;
    r.y = a.w * b.y - a.x * b.z + a.y * b.w + a.z * b.x;
    r.z = a.w * b.z + a.x * b.y - a.y * b.x + a.z * b.w;
    return r;
}

// conj(a) * b
__device__ __forceinline__ float4 qcmul(float4 a, float4 b) {
    float4 r;
    r.w = a.w * b.w + a.x * b.x + a.y * b.y + a.z * b.z;
    r.x = a.w * b.x - a.x * b.w - a.y * b.z + a.z * b.y;
    r.y = a.w * b.y + a.x * b.z - a.y * b.w - a.z * b.x;
    r.z = a.w * b.z - a.x * b.y + a.y * b.x - a.z * b.w;
    return r;
}

// exp of small rotation vector (|v| <= ~0.1), Taylor in (a/2)^2, err ~1e-12
__device__ __forceinline__ float4 qexp_small(float x, float y, float z) {
    float a2 = fmaf(x, x, fmaf(y, y, z * z));
    float t2 = 0.25f * a2;
    float w  = fmaf(t2, fmaf(t2, (1.0f / 24.0f), -0.5f), 1.0f);           // cos(a/2)
    float k  = fmaf(t2, fmaf(t2, (0.5f / 120.0f), -(0.5f / 6.0f)), 0.5f); // sin(a/2)/a
    return make_float4(k * x, k * y, k * z, w);
}

// full-range exp via MUFU (X = exp(xs); |xs| bounded so a/2 well inside MUFU range)
__device__ __forceinline__ float4 qexp_full(float x, float y, float z) {
    float a2 = fmaf(x, x, fmaf(y, y, z * z));
    float a  = sqrtf(fmaxf(a2, 1e-16f));
    float h  = 0.5f * a;
    float s  = __sinf(h);
    float c  = __cosf(h);
    float k  = __fdividef(s, a);
    if (a2 < 1e-8f) k = 0.5f;
    return make_float4(k * x, k * y, k * z, c);
}

// acos for x in [0,1]: A&S 4.4.45, abs err <= 6.7e-5 rad, ~6 instr
__device__ __forceinline__ float acos01(float x) {
    float p = fmaf(x, -0.0187293f, 0.0742610f);
    p = fmaf(p, x, -0.2121144f);
    p = fmaf(p, x, 1.5707288f);
    return sqrtf(1.0f - x) * p;
}

// acos for x in [-1,1] (branch-free select)
__device__ __forceinline__ float acos_full(float x) {
    float r = acos01(fabsf(x));
    return (x < 0.0f) ? (PI_F - r) : r;
}

__device__ __forceinline__ float huber_elem(float r) {
    float ar = fabsf(r);
    return (ar < 1.0f) ? 0.5f * r * r : ar - 0.5f;
}

__global__ __launch_bounds__(THREADS)
void loss_kernel(const float* __restrict__ xs, const float* __restrict__ hat,
                 float* __restrict__ out) {
    __shared__ float4 s_h[4][GPB];          // SoA: conflict-free phase-B reads

    const int tid = threadIdx.x;
    const int t   = tid & 3;
    const int gb  = tid >> 2;
    const int n   = blockIdx.x * GPB + gb;

    // ---- issue phase-B xs load EARLY so its DRAM latency hides under phase A
    float4 xv = make_float4(0.f, 0.f, 0.f, 0.f);
    if (tid < GPB)
        xv = reinterpret_cast<const float4*>(xs)[(size_t)(blockIdx.x * GPB + tid) * 12];

    // ================= Phase A: all 256 threads, no divergence =================
    {
        const float4* hp = reinterpret_cast<const float4*>(hat) + (size_t)n * 12 + t * 3;
        float4 v0 = hp[0], v1 = hp[1], v2 = hp[2];
        float4 qa = qexp_small(DT * v0.x, DT * v0.y, DT * v0.z);
        float4 qb = qexp_small(DT * v0.w, DT * v1.x, DT * v1.y);
        float4 qc = qexp_small(DT * v1.z, DT * v1.w, DT * v2.x);
        float4 qd = qexp_small(DT * v2.y, DT * v2.z, DT * v2.w);
        s_h[t][gb] = qmul(qmul(qa, qb), qmul(qc, qd));
    }
    __syncthreads();

    // ---- warps 2..7: done (free their issue slots immediately)
    if (tid >= GPB) return;

    // ================= Phase B: warps 0-1, one lane per group ==================
    const int g  = tid;
    const int ng = blockIdx.x * GPB + g;

    float4 h0 = s_h[0][g], h1 = s_h[1][g], h2 = s_h[2][g], h3 = s_h[3][g];
    float4 Om = qmul(qmul(h0, h1), qmul(h2, h3));
    float4 X  = qexp_full(xv.x, xv.y, xv.z);

    // AOE: angle = 2*acos(|<qOm,qX>|)
    float d  = fmaf(Om.w, X.w, fmaf(Om.x, X.x, fmaf(Om.y, X.y, Om.z * X.z)));
    float ch = fminf(fabsf(d), 1.0f);
    float ang = 2.0f * acos01(ch);
    float aoe = ang * ang;
    float hub = 0.0f;

    // pyramid level: pair (2m, 2m+1) = adjacent lanes (pairs never cross warps)
    float4 Omo, Xo;
    Omo.x = __shfl_down_sync(0xffffffffu, Om.x, 1);
    Omo.y = __shfl_down_sync(0xffffffffu, Om.y, 1);
    Omo.z = __shfl_down_sync(0xffffffffu, Om.z, 1);
    Omo.w = __shfl_down_sync(0xffffffffu, Om.w, 1);
    Xo.x  = __shfl_down_sync(0xffffffffu, X.x, 1);
    Xo.y  = __shfl_down_sync(0xffffffffu, X.y, 1);
    Xo.z  = __shfl_down_sync(0xffffffffu, X.z, 1);
    Xo.w  = __shfl_down_sync(0xffffffffu, X.w, 1);

    if ((ng & 1) == 0) {
        int m = ng >> 1;
        if ((m & PAIRS_MASK) >= N0_DROP) {
            float4 Op  = qmul(Om, Omo);
            float4 Xp  = qmul(X, Xo);
            float4 rel = qcmul(Op, Xp);          // Op^T * Xp
            float w  = rel.w;
            float ct = fminf(fmaxf(fmaf(2.0f * w, w, -1.0f), -1.0f), 1.0f);
            float an = acos_full(ct);
            float sv = sqrtf(fmaxf(1.0f - w * w, 0.0f));
            float st = 2.0f * fabsf(w) * sv;     // sin(theta)
            float factor = (st < 1e-6f) ? 0.5f : __fdividef(an, 2.0f * st);
            float fh = factor * 4.0f * w * INV_HUBER;
            hub = huber_elem(fh * rel.x) + huber_elem(fh * rel.y) + huber_elem(fh * rel.z);
        }
    }

    // ---- warp reduction; each phase-B warp REDs its own scaled total
#pragma unroll
    for (int o = 16; o > 0; o >>= 1) {
        aoe += __shfl_xor_sync(0xffffffffu, aoe, o);
        hub += __shfl_xor_sync(0xffffffffu, hub, o);
    }
    if ((tid & 31) == 0)
        atomicAdd(out, fmaf(AOE_COEF, aoe, HUB_COEF * hub));   // RED.ADD.F32

}

extern "C" void kernel_launch(void* const* d_in, const int* in_sizes, int n_in,
                              void* d_out, int out_size) {
    const float* xs  = (const float*)d_in[0];
    const float* hat = (const float*)d_in[1];
    (void)in_sizes; (void)n_in; (void)out_size;
    cudaMemsetAsync(d_out, 0, sizeof(float), (cudaStream_t)0);  // graph-capturable memset node
    loss_kernel<<<NBLOCKS, THREADS, 0, (cudaStream_t)0>>>(xs, hat, (float*)d_out);
}

// round 12
// speedup vs baseline: 1.1809x; 1.1809x over previous
#include <cuda_runtime.h>
#include <math.h>

// Fixed shapes: xs/hat_xs are (16, 65536, 3) float32 -> 1,048,576 vectors, 65,536 groups of 16.
#define NGROUPS      65536
#define GPB          64                     // groups per block
#define THREADS      256                    // 4 threads per group in phase A
#define NBLOCKS      (NGROUPS / GPB)        // 1024
#define PAIRS_MASK   2047
#define N0_DROP      5
#define DT           0.01f
#define INV_HUBER    200.0f
#define AOE_COEF     (0.2f / 65536.0f)
#define HUB_COEF     (1.25f / 98064.0f)     // 0.1*W*HUBER^2/2 / (16*2043*3)
#define PI_F         3.14159265358979f

// q = (x,y,z,w), w scalar. Hamilton product (R(a)R(b)).
__device__ __forceinline__ float4 qmul(float4 a, float4 b) {
    float4 r;
    r.w = a.w * b.w - a.x * b.x - a.y * b.y - a.z * b.z;
    r.x = a.w * b.x + a.x * b.w + a.y * b.z - a.z * b.y;
    r.y = a.w * b.y - a.x * b.z + a.y * b.w + a.z * b.x;
    r.z = a.w * b.z + a.x * b.y - a.y * b.x + a.z * b.w;
    return r;
}

// conj(a) * b
__device__ __forceinline__ float4 qcmul(float4 a, float4 b) {
    float4 r;
    r.w = a.w * b.w + a.x * b.x + a.y * b.y + a.z * b.z;
    r.x = a.w * b.x - a.x * b.w - a.y * b.z + a.z * b.y;
    r.y = a.w * b.y + a.x * b.z - a.y * b.w - a.z * b.x;
    r.z = a.w * b.z - a.x * b.y + a.y * b.x - a.z * b.w;
    return r;
}

// exp of small rotation vector (|v| <= ~0.1), Taylor in (a/2)^2, err ~1e-12
__device__ __forceinline__ float4 qexp_small(float x, float y, float z) {
    float a2 = fmaf(x, x, fmaf(y, y, z * z));
    float t2 = 0.25f * a2;
    float w  = fmaf(t2, fmaf(t2, (1.0f / 24.0f), -0.5f), 1.0f);           // cos(a/2)
    float k  = fmaf(t2, fmaf(t2, (0.5f / 120.0f), -(0.5f / 6.0f)), 0.5f); // sin(a/2)/a
    return make_float4(k * x, k * y, k * z, w);
}

// full-range exp via MUFU (X = exp(xs); |xs| bounded so a/2 well inside MUFU range)
__device__ __forceinline__ float4 qexp_full(float x, float y, float z) {
    float a2 = fmaf(x, x, fmaf(y, y, z * z));
    float a  = sqrtf(fmaxf(a2, 1e-16f));
    float h  = 0.5f * a;
    float s  = __sinf(h);
    float c  = __cosf(h);
    float k  = __fdividef(s, a);
    if (a2 < 1e-8f) k = 0.5f;
    return make_float4(k * x, k * y, k * z, c);
}

// acos for x in [0,1]: A&S 4.4.45, abs err <= 6.7e-5 rad, ~6 instr
__device__ __forceinline__ float acos01(float x) {
    float p = fmaf(x, -0.0187293f, 0.0742610f);
    p = fmaf(p, x, -0.2121144f);
    p = fmaf(p, x, 1.5707288f);
    return sqrtf(1.0f - x) * p;
}

// acos for x in [-1,1] (branch-free select)
__device__ __forceinline__ float acos_full(float x) {
    float r = acos01(fabsf(x));
    return (x < 0.0f) ? (PI_F - r) : r;
}

__device__ __forceinline__ float huber_elem(float r) {
    float ar = fabsf(r);
    return (ar < 1.0f) ? 0.5f * r * r : ar - 0.5f;
}

__global__ __launch_bounds__(THREADS)
void loss_kernel(const float* __restrict__ xs, const float* __restrict__ hat,
                 float* __restrict__ out) {
    __shared__ float4 s_h[THREADS];
    __shared__ float  s_aoe[2], s_hub[2];

    const int tid = threadIdx.x;
    const int t   = tid & 3;
    const int gb  = tid >> 2;
    const int n   = blockIdx.x * GPB + gb;

    // ---- issue phase-B xs load EARLY so its DRAM latency hides under phase A
    float4 xv = make_float4(0.f, 0.f, 0.f, 0.f);
    if (tid < GPB)
        xv = reinterpret_cast<const float4*>(xs)[(size_t)(blockIdx.x * GPB + tid) * 12];

    // ================= Phase A: all 256 threads, no divergence =================
    {
        const float4* hp = reinterpret_cast<const float4*>(hat) + (size_t)n * 12 + t * 3;
        float4 v0 = hp[0], v1 = hp[1], v2 = hp[2];
        float4 qa = qexp_small(DT * v0.x, DT * v0.y, DT * v0.z);
        float4 qb = qexp_small(DT * v0.w, DT * v1.x, DT * v1.y);
        float4 qc = qexp_small(DT * v1.z, DT * v1.w, DT * v2.x);
        float4 qd = qexp_small(DT * v2.y, DT * v2.z, DT * v2.w);
        s_h[tid] = qmul(qmul(qa, qb), qmul(qc, qd));
    }
    __syncthreads();

    // ================= Phase B: warps 0-1, one lane per group ==================
    if (tid < GPB) {
        const int g  = tid;
        const int ng = blockIdx.x * GPB + g;

        float4 h0 = s_h[4 * g], h1 = s_h[4 * g + 1], h2 = s_h[4 * g + 2], h3 = s_h[4 * g + 3];
        float4 Om = qmul(qmul(h0, h1), qmul(h2, h3));
        float4 X  = qexp_full(xv.x, xv.y, xv.z);

        // AOE: angle = 2*acos(|<qOm,qX>|)
        float d  = fmaf(Om.w, X.w, fmaf(Om.x, X.x, fmaf(Om.y, X.y, Om.z * X.z)));
        float ch = fminf(fabsf(d), 1.0f);
        float ang = 2.0f * acos01(ch);
        float aoe = ang * ang;
        float hub = 0.0f;

        // pyramid level: pair (2m, 2m+1) = adjacent lanes
        float4 Omo, Xo;
        Omo.x = __shfl_down_sync(0xffffffffu, Om.x, 1);
        Omo.y = __shfl_down_sync(0xffffffffu, Om.y, 1);
        Omo.z = __shfl_down_sync(0xffffffffu, Om.z, 1);
        Omo.w = __shfl_down_sync(0xffffffffu, Om.w, 1);
        Xo.x  = __shfl_down_sync(0xffffffffu, X.x, 1);
        Xo.y  = __shfl_down_sync(0xffffffffu, X.y, 1);
        Xo.z  = __shfl_down_sync(0xffffffffu, X.z, 1);
        Xo.w  = __shfl_down_sync(0xffffffffu, X.w, 1);

        if ((ng & 1) == 0) {
            int m = ng >> 1;
            if ((m & PAIRS_MASK) >= N0_DROP) {
                float4 Op  = qmul(Om, Omo);
                float4 Xp  = qmul(X, Xo);
                float4 rel = qcmul(Op, Xp);
                float w  = rel.w;
                float ct = fminf(fmaxf(fmaf(2.0f * w, w, -1.0f), -1.0f), 1.0f);
                float an = acos_full(ct);
                float sv = sqrtf(fmaxf(1.0f - w * w, 0.0f));
                float st = 2.0f * fabsf(w) * sv;     // sin(theta)
                float factor = (st < 1e-6f) ? 0.5f : __fdividef(an, 2.0f * st);
                float fh = factor * 4.0f * w * INV_HUBER;
                hub = huber_elem(fh * rel.x) + huber_elem(fh * rel.y) + huber_elem(fh * rel.z);
            }
        }

#pragma unroll
        for (int o = 16; o > 0; o >>= 1) {
            aoe += __shfl_xor_sync(0xffffffffu, aoe, o);
            hub += __shfl_xor_sync(0xffffffffu, hub, o);
        }
        if ((tid & 31) == 0) { s_aoe[tid >> 5] = aoe; s_hub[tid >> 5] = hub; }
    }
    __syncthreads();

    // ---- fire-and-forget: scaled per-block contribution straight into out[0]
    // (out[0] zeroed by the memset graph node before this kernel)
    if (tid == 0) {
        float part = fmaf(AOE_COEF, s_aoe[0] + s_aoe[1],
                          HUB_COEF * (s_hub[0] + s_hub[1]));
        atomicAdd(out, part);   // RED.ADD.F32, no return, no ordering needed
    }
}

extern "C" void kernel_launch(void* const* d_in, const int* in_sizes, int n_in,
                              void* d_out, int out_size) {
    const float* xs  = (const float*)d_in[0];
    const float* hat = (const float*)d_in[1];
    (void)in_sizes; (void)n_in; (void)out_size;
    cudaMemsetAsync(d_out, 0, sizeof(float), (cudaStream_t)0);  // graph-capturable memset node
    loss_kernel<<<NBLOCKS, THREADS, 0, (cudaStream_t)0>>>(xs, hat, (float*)d_out);
}